// round 16
// baseline (speedup 1.0000x reference)
#include <cuda_runtime.h>
#include <math.h>
#include <stdint.h>

// Problem constants
#define BB 512
#define NN 64
#define EE 512
#define AA 16
#define ITERS 8
#define TPB 1024         // one fat CTA per batch; occ 1 (regs + smem force it)
#define NHW (TPB / 16)   // 64 half-warps
#define EINV (1.0f / 512.0f)
#define STAGE_WORDS (2 * 32 * 2 * 256)   // 2 bufs x 32 warps x 2 tiles x 1KB = 128KB

// Adjacency (CSR, ascending edge order) -- built once per launch on device.
__device__ int g_to_off[NN + 1], g_from_off[NN + 1];
__device__ int g_to_lst[EE], g_from_lst[EE];

__global__ void build_adj_kernel(const int* __restrict__ ef, const int* __restrict__ et) {
    __shared__ int sf[EE], st[EE];
    __shared__ int cto[NN], cfr[NN];
    int t = threadIdx.x;
    for (int e = t; e < EE; e += blockDim.x) { sf[e] = ef[e]; st[e] = et[e]; }
    __syncthreads();
    if (t < NN) {
        int ct = 0, cf = 0;
        for (int e = 0; e < EE; e++) { ct += (st[e] == t); cf += (sf[e] == t); }
        cto[t] = ct; cfr[t] = cf;
    }
    __syncthreads();
    if (t == 0) {
        int a = 0, b = 0;
        for (int n = 0; n < NN; n++) {
            g_to_off[n] = a; a += cto[n];
            g_from_off[n] = b; b += cfr[n];
        }
        g_to_off[NN] = a; g_from_off[NN] = b;
    }
    __syncthreads();
    if (t < NN) {
        int ot = g_to_off[t], of = g_from_off[t];
        for (int e = 0; e < EE; e++) {
            if (st[e] == t) g_to_lst[ot++] = e;
            if (sf[e] == t) g_from_lst[of++] = e;
        }
    }
}

// SMEM words: stage 32768 + q0 1024 + q 1024 + qT 1024 + mf 8192 + mbT 8192 +
// red 16 + red_node 2 + a_cur 64 + ef 512 + et 512 + offs 130 + lsts 1024
// = 54472 words = 217888 bytes (~213KB <= 227KB dynamic max)
#define SMEM_WORDS (STAGE_WORDS + 1024 + 1024 + 1024 + 8192 + 8192 + 16 + 2 + 64 + 512 + 512 + 65 + 65 + 512 + 512)
#define SMEM_BYTES (SMEM_WORDS * 4)

__device__ __forceinline__ float4 f4_sub(float4 a, float4 b) {
    float4 r;
    r.x = a.x - b.x; r.y = a.y - b.y; r.z = a.z - b.z; r.w = a.w - b.w;
    return r;
}
// max over 4 elements of (T*EINV + u[j])  -- exact: T*EINV product exact,
// single rounding per add, fmax exactly associative.
__device__ __forceinline__ float seg_max(float4 T, float4 u) {
    float a = fmaxf(fmaf(T.x, EINV, u.x), fmaf(T.y, EINV, u.y));
    float b = fmaxf(fmaf(T.z, EINV, u.z), fmaf(T.w, EINV, u.w));
    return fmaxf(a, b);
}

__global__ __launch_bounds__(TPB, 1)
void dcg_kernel(const float* __restrict__ nodev, const float* __restrict__ edgev,
                const int* __restrict__ ef, const int* __restrict__ et,
                float* __restrict__ out)
{
    extern __shared__ float smem[];
    float* stage   = smem;                        // 32768 (16B aligned)
    float* q0      = stage + STAGE_WORDS;         // 1024
    float* q       = q0 + 1024;                   // 1024 (normal layout)
    float* qT      = q + 1024;                    // 1024 (transposed)
    float* mf      = qT + 1024;                   // 8192 (normal layout)
    float* mbT     = mf + 8192;                   // 8192 (transposed)
    float* red     = mbT + 8192;                  // 16
    float* red_node = red + 16;                   // 2
    int* a_cur   = (int*)(red_node + 2);          // 64
    int* ef_s    = a_cur + 64;                    // 512
    int* et_s    = ef_s + EE;                     // 512
    int* to_off  = et_s + EE;                     // 65
    int* from_off = to_off + (NN + 1);            // 65
    int* to_lst  = from_off + (NN + 1);           // 512
    int* from_lst = to_lst + EE;                  // 512

    const int tid    = threadIdx.x;
    const int b      = blockIdx.x;
    const int halfid = tid >> 4;        // 0..63
    const int hl     = tid & 15;
    const int sseg   = hl & 3;
    const int kgrp   = hl >> 2;
    const unsigned hmask = 0xFFFFu << ((halfid & 1) * 16);
    const int warp = tid >> 5;
    const int lane = tid & 31;
    const int hsel = halfid & 1;        // which tile slot within warp
    const int permS = ((sseg & 1) << 1) | (sseg >> 1);
    const int permK = ((kgrp & 1) << 1) | (kgrp >> 1);
    const int tpos = 4 * (hl & 3) + (hl >> 2);

    const float* nb    = nodev + (size_t)b * NN * AA;
    const float* ebase = edgev + (size_t)b * EE * AA * AA;

    // ---- init
    {
        int i = tid, n16 = i & ~15, a = i & 15;
        float v = nb[i] * 0.015625f;   // /64 exact
        q0[i] = v; q[i] = v;
        qT[n16 + 4 * (a & 3) + (a >> 2)] = v;
    }
    for (int i = tid; i < EE * AA; i += TPB) { mf[i] = 0.f; mbT[i] = 0.f; }
    if (tid < EE) {
        ef_s[tid] = ef[tid]; et_s[tid] = et[tid];
        to_lst[tid] = g_to_lst[tid]; from_lst[tid] = g_from_lst[tid];
    }
    if (tid >= EE && tid < EE + NN + 1) {
        int i = tid - EE;
        to_off[i] = g_to_off[i]; from_off[i] = g_from_off[i];
    }
    __syncthreads();

    // ---- stage pass tiles: warp w stages edges {2w, 2w+1} + 64*p via cp.async.cg
    auto stage_pass = [&](int seq) {
        const int p = seq & 7;
        const int f = seq & 1;
        float* s0 = stage + ((f * 32 + warp) * 2 + 0) * 256;
        float* s1 = stage + ((f * 32 + warp) * 2 + 1) * 256;
        const float* gA = ebase + (size_t)(2 * warp + 0 + 64 * p) * 256;
        const float* gB = ebase + (size_t)(2 * warp + 1 + 64 * p) * 256;
        unsigned dA0 = (unsigned)__cvta_generic_to_shared(s0 + lane * 4);
        unsigned dA1 = (unsigned)__cvta_generic_to_shared(s0 + (lane + 32) * 4);
        unsigned dB0 = (unsigned)__cvta_generic_to_shared(s1 + lane * 4);
        unsigned dB1 = (unsigned)__cvta_generic_to_shared(s1 + (lane + 32) * 4);
        asm volatile("cp.async.cg.shared.global [%0], [%1], 16;\n" :: "r"(dA0), "l"(gA + lane * 4) : "memory");
        asm volatile("cp.async.cg.shared.global [%0], [%1], 16;\n" :: "r"(dA1), "l"(gA + (lane + 32) * 4) : "memory");
        asm volatile("cp.async.cg.shared.global [%0], [%1], 16;\n" :: "r"(dB0), "l"(gB + lane * 4) : "memory");
        asm volatile("cp.async.cg.shared.global [%0], [%1], 16;\n" :: "r"(dB1), "l"(gB + (lane + 32) * 4) : "memory");
        asm volatile("cp.async.commit_group;\n" ::: "memory");
    };

    // ---- initial greedy action: argmax of q0 per node (lowest index ties)
    {
        const int n = halfid;
        float bv = q0[n * AA + hl]; int bi = hl;
        #pragma unroll
        for (int o = 8; o; o >>= 1) {
            float ov = __shfl_xor_sync(hmask, bv, o, 16);
            int   oi = __shfl_xor_sync(hmask, bi, o, 16);
            if (ov > bv || (ov == bv && oi < bi)) { bv = ov; bi = oi; }
        }
        if (hl == 0) a_cur[n] = bi;
    }
    __syncthreads();

    stage_pass(0);   // prime the pipeline

    float qmax_reg = 0.f;   // uniform across threads
    int   abest_reg = 0;    // per-thread (meaningful for tid < NN)
    int   snap = 0;

    // ================= main loop: 2 barriers per iteration ================
    for (int it = 0; it < ITERS; it++) {
        // -- issue eval-gather loads for the CURRENT a_cur (overlaps phase 1)
        float ev = 0.f, nv = 0.f;
        if (tid < EE) {
            int e  = tid;
            int af = a_cur[ef_s[e]];
            int at = a_cur[et_s[e]];
            ev = ebase[(size_t)e * 256 + af * 16 + at];
        }
        if (tid < NN) {
            snap = a_cur[tid];
            nv = q0[tid * AA + snap] * 64.0f;   // node_vals exact
        }

        // -- phase 1: 8 passes, tiles via staged smem (proven R12 math)
        for (int p = 0; p < 8; ++p) {
            const int seq = it * 8 + p;
            if (seq < ITERS * 8 - 1) {
                stage_pass(seq + 1);
                asm volatile("cp.async.wait_group 1;\n" ::: "memory");
            } else {
                asm volatile("cp.async.wait_group 0;\n" ::: "memory");
            }
            __syncwarp();

            const int e = halfid + 64 * p;
            const int nf = ef_s[e], nt = et_s[e];

            // hoisted old-state loads (before any store this pass)
            const float4 qnt4 = *(const float4*)(q  + nt * AA + 4 * sseg);
            const float4 mfo4 = *(const float4*)(mf + e  * AA + 4 * sseg);
            const float4 ubv  = f4_sub(qnt4, mfo4);
            const float4 ufq  = *(const float4*)(qT  + nf * AA + 4 * kgrp);
            const float4 ufm  = *(const float4*)(mbT + e  * AA + 4 * kgrp);
            const float uf0 = ufq.x - ufm.x;
            const float uf1 = ufq.y - ufm.y;
            const float uf2 = ufq.z - ufm.z;
            const float uf3 = ufq.w - ufm.w;

            // tile from staged smem (identical bytes to gmem tile)
            const float4* g4 = (const float4*)(stage + (((p & 1) * 32 + warp) * 2 + hsel) * 256);
            const float4 T0 = g4[ 0 + hl];
            const float4 T1 = g4[16 + hl];
            const float4 T2 = g4[32 + hl];
            const float4 T3 = g4[48 + hl];

            // mb partials + reduce-scatter over s (xor 1 then 2)
            float p0 = seg_max(T0, ubv);
            float p1 = seg_max(T1, ubv);
            float p2 = seg_max(T2, ubv);
            float p3 = seg_max(T3, ubv);
            float mbv;
            {
                const bool s0 = (sseg & 1) != 0;
                float send0 = s0 ? p0 : p2, send1 = s0 ? p1 : p3;
                float keep0 = s0 ? p2 : p0, keep1 = s0 ? p3 : p1;
                float r0 = __shfl_xor_sync(hmask, send0, 1, 16);
                float r1 = __shfl_xor_sync(hmask, send1, 1, 16);
                float a0 = fmaxf(keep0, r0), a1 = fmaxf(keep1, r1);
                const bool s1 = (sseg & 2) != 0;
                float send = s1 ? a0 : a1, keep = s1 ? a1 : a0;
                float r = __shfl_xor_sync(hmask, send, 2, 16);
                mbv = fmaxf(keep, r);
            }

            // mf candidates + reduce-scatter over k (xor 4 then 8)
            float cx = fmaxf(fmaxf(fmaf(T0.x, EINV, uf0), fmaf(T1.x, EINV, uf1)),
                             fmaxf(fmaf(T2.x, EINV, uf2), fmaf(T3.x, EINV, uf3)));
            float cy = fmaxf(fmaxf(fmaf(T0.y, EINV, uf0), fmaf(T1.y, EINV, uf1)),
                             fmaxf(fmaf(T2.y, EINV, uf2), fmaf(T3.y, EINV, uf3)));
            float cz = fmaxf(fmaxf(fmaf(T0.z, EINV, uf0), fmaf(T1.z, EINV, uf1)),
                             fmaxf(fmaf(T2.z, EINV, uf2), fmaf(T3.z, EINV, uf3)));
            float cw = fmaxf(fmaxf(fmaf(T0.w, EINV, uf0), fmaf(T1.w, EINV, uf1)),
                             fmaxf(fmaf(T2.w, EINV, uf2), fmaf(T3.w, EINV, uf3)));
            float mfv;
            {
                const bool k0 = (kgrp & 1) != 0;
                float send0 = k0 ? cx : cz, send1 = k0 ? cy : cw;
                float keep0 = k0 ? cz : cx, keep1 = k0 ? cw : cy;
                float r0 = __shfl_xor_sync(hmask, send0, 4, 16);
                float r1 = __shfl_xor_sync(hmask, send1, 4, 16);
                float a0 = fmaxf(keep0, r0), a1 = fmaxf(keep1, r1);
                const bool k1 = (kgrp & 2) != 0;
                float send = k1 ? a0 : a1, keep = k1 ? a1 : a0;
                float r = __shfl_xor_sync(hmask, send, 8, 16);
                mfv = fmaxf(keep, r);
            }

            // means with the pinned association trees
            float smb = mbv;
            smb += __shfl_xor_sync(hmask, smb, 1, 16);
            smb += __shfl_xor_sync(hmask, smb, 2, 16);
            smb += __shfl_xor_sync(hmask, smb, 8, 16);
            smb += __shfl_xor_sync(hmask, smb, 4, 16);
            float smf = mfv;
            smf += __shfl_xor_sync(hmask, smf, 2, 16);
            smf += __shfl_xor_sync(hmask, smf, 1, 16);
            smf += __shfl_xor_sync(hmask, smf, 4, 16);
            smf += __shfl_xor_sync(hmask, smf, 8, 16);

            // stores (bijective; butterflies ordered old-state loads first)
            mbT[e * AA + 4 * kgrp + permS] = mbv - smb * 0.0625f;
            mf [e * AA + 4 * sseg + permK] = mfv - smf * 0.0625f;
        }

        // eval reductions (identical association to the proven sequence)
        if (tid < EE) {
            #pragma unroll
            for (int o = 16; o; o >>= 1) ev += __shfl_xor_sync(0xffffffffu, ev, o, 32);
            if (lane == 0) red[warp] = ev;
        }
        if (tid < NN) {
            #pragma unroll
            for (int o = 16; o; o >>= 1) nv += __shfl_xor_sync(0xffffffffu, nv, o, 32);
            if (lane == 0) red_node[warp] = nv;
        }
        __syncthreads();

        // -- redundant finalize (all threads, identical association -> uniform)
        {
            float es = 0.f;
            #pragma unroll
            for (int w = 0; w < 16; w++) es += red[w];
            float ns = red_node[0] + red_node[1];
            float qv = ns * (1.0f / 64.0f) + es * (1.0f / 512.0f);
            bool upd = (it == 0) || (qv > qmax_reg);
            if (upd) { qmax_reg = qv; if (tid < NN) abest_reg = snap; }
        }

        // -- phase 2: q update + argmax (node n = halfid)
        {
            const int n = halfid;
            float acc = q0[n * AA + hl];
            int o0 = to_off[n], o1 = to_off[n + 1];
            for (int i = o0; i < o1; i++) acc += mf[to_lst[i] * AA + hl];
            o0 = from_off[n]; o1 = from_off[n + 1];
            for (int i = o0; i < o1; i++) acc += mbT[from_lst[i] * AA + tpos];
            q[n * AA + hl] = acc;
            qT[n * AA + tpos] = acc;
            float bv = acc; int bi = hl;
            #pragma unroll
            for (int o = 8; o; o >>= 1) {
                float ov = __shfl_xor_sync(hmask, bv, o, 16);
                int   oi = __shfl_xor_sync(hmask, bi, o, 16);
                if (ov > bv || (ov == bv && oi < bi)) { bv = ov; bi = oi; }
            }
            if (hl == 0) a_cur[n] = bi;
        }
        __syncthreads();
    }

    // ---- tail: evaluate the final iteration's greedy action
    {
        float ev = 0.f, nv = 0.f;
        if (tid < EE) {
            int e  = tid;
            int af = a_cur[ef_s[e]];
            int at = a_cur[et_s[e]];
            ev = ebase[(size_t)e * 256 + af * 16 + at];
            #pragma unroll
            for (int o = 16; o; o >>= 1) ev += __shfl_xor_sync(0xffffffffu, ev, o, 32);
            if (lane == 0) red[warp] = ev;
        }
        if (tid < NN) {
            snap = a_cur[tid];
            nv = q0[tid * AA + snap] * 64.0f;
            #pragma unroll
            for (int o = 16; o; o >>= 1) nv += __shfl_xor_sync(0xffffffffu, nv, o, 32);
            if (lane == 0) red_node[warp] = nv;
        }
        __syncthreads();
        float es = 0.f;
        #pragma unroll
        for (int w = 0; w < 16; w++) es += red[w];
        float ns = red_node[0] + red_node[1];
        float qv = ns * (1.0f / 64.0f) + es * (1.0f / 512.0f);
        bool upd = (qv > qmax_reg);
        if (upd) { qmax_reg = qv; if (tid < NN) abest_reg = snap; }
    }

    // ---- output: concat(q_max[B], float(a_max[B,N]))
    if (tid == 0) out[b] = qmax_reg;
    if (tid < NN) out[BB + (size_t)b * NN + tid] = (float)abest_reg;
}

extern "C" void kernel_launch(void* const* d_in, const int* in_sizes, int n_in,
                              void* d_out, int out_size)
{
    const float* nodev = (const float*)d_in[0];   // (B,N,A) f32
    const float* edgev = (const float*)d_in[1];   // (B,E,A,A) f32
    const int*   ef    = (const int*)d_in[2];     // (E,) i32
    const int*   et    = (const int*)d_in[3];     // (E,) i32
    float* out = (float*)d_out;

    static bool attr_set = false;
    if (!attr_set) {
        cudaFuncSetAttribute(dcg_kernel, cudaFuncAttributeMaxDynamicSharedMemorySize, SMEM_BYTES);
        attr_set = true;
    }

    build_adj_kernel<<<1, 64>>>(ef, et);
    dcg_kernel<<<BB, TPB, SMEM_BYTES>>>(nodev, edgev, ef, et, out);
}